// round 14
// baseline (speedup 1.0000x reference)
#include <cuda_runtime.h>
#include <cuda_bf16.h>
#include <math.h>
#include <stdint.h>

// Problem dims
constexpr int NB  = 2;
constexpr int NS  = 1024;
constexpr int ND  = 512;
constexpr int NH  = 8;
constexpr int NDH = 64;
constexpr int NL  = 6;
constexpr int NV  = 50257;
constexpr int NBS = NB * NS;      // 2048
constexpr int NFF = 4 * ND;       // 2048
constexpr int NPART = (NV + 127) / 128;   // 393 head n-tiles
constexpr int PSTRIDE = 400;
constexpr float INV_SCALE = 0.04419417382415922f; // 1/sqrt(512)

// ---------------- scratch (static device globals; no allocation) -------------
__device__ float g_x[NBS * ND];
__device__ float g_h[NBS * ND];
__device__ float g_q[NBS * ND];
__device__ float g_k[NBS * ND];
__device__ float g_v[NBS * ND];
__device__ float g_o[NBS * ND];
__device__ float g_ff[NBS * NFF];
__device__ float2 g_part[NBS * PSTRIDE];  // (max, sum) logsumexp partials
__device__ float g_nll[NBS];

__device__ __forceinline__ float to_tf32(float x) {
    uint32_t u;
    asm("cvt.rna.tf32.f32 %0, %1;" : "=r"(u) : "f"(x));
    return __uint_as_float(u);
}

// Fragment-friendly column permutations.
__device__ __forceinline__ int ac16(int m) {
    return (m & ~15) | ((m & 7) << 1) | ((m >> 3) & 1);
}
__device__ __forceinline__ int bc32(int n) {
    return (n & ~31) | ((n & 7) << 2) | ((n >> 3) & 3);
}
__device__ __forceinline__ int bc64p(int n) {
    return ((n & 7) << 3) | ((n >> 3) & 7);
}

// ---------------- embedding --------------------------------------------------
__global__ void embed_k(const int* __restrict__ idx, const int* __restrict__ mask,
                        const float* __restrict__ tok, const float* __restrict__ pos,
                        float* __restrict__ x) {
    int row = blockIdx.x;
    int b = row / NS, s = row % NS;
    int t = idx[b * (NS + 1) + s];
    float m = (float)mask[row];
    const float* tr = tok + (size_t)t * ND;
    const float* pr = pos + (size_t)s * ND;
    float* xr = x + (size_t)row * ND;
    for (int d = threadIdx.x; d < ND; d += blockDim.x)
        xr[d] = (tr[d] + pr[d]) * m;
}

// ---------------- layernorm --------------------------------------------------
__global__ __launch_bounds__(256) void ln_k(const float* __restrict__ x,
                                            const float* __restrict__ g,
                                            const float* __restrict__ be,
                                            float* __restrict__ out) {
    int row = blockIdx.x;
    int tid = threadIdx.x;
    const float* xr = x + (size_t)row * ND;
    float v0 = xr[tid], v1 = xr[tid + 256];
    __shared__ float red[256];
    red[tid] = v0 + v1;
    __syncthreads();
    for (int o = 128; o > 0; o >>= 1) { if (tid < o) red[tid] += red[tid + o]; __syncthreads(); }
    float mean = red[0] * (1.0f / ND);
    __syncthreads();
    float d0 = v0 - mean, d1 = v1 - mean;
    red[tid] = d0 * d0 + d1 * d1;
    __syncthreads();
    for (int o = 128; o > 0; o >>= 1) { if (tid < o) red[tid] += red[tid + o]; __syncthreads(); }
    float inv = rsqrtf(red[0] * (1.0f / ND) + 1e-5f);
    float* orow = out + (size_t)row * ND;
    orow[tid]       = d0 * inv * g[tid]       + be[tid];
    orow[tid + 256] = d1 * inv * g[tid + 256] + be[tid + 256];
}

// ---------------- TF32 tensor-core GEMM, double-buffered, vectorized frags ---
// LOSSP: write per-row (max, sumexp) partials over this CTA's N-slice (head).
template <int ACT, bool HAS_BIAS, bool HAS_RES, int BN, bool BALIGN, bool LOSSP>
__device__ __forceinline__ void gemm_body(const float* __restrict__ A,
                                          const float* __restrict__ Bm,
                                          const float* __restrict__ bias,
                                          const float* __restrict__ Res,
                                          float* __restrict__ C,
                                          float2* __restrict__ part,
                                          int M, int N, int K,
                                          int m0, int n0) {
    constexpr int BM = 128, BK = 16;
    constexpr int WARPS_N = (BN == 128) ? 4 : 2;
    constexpr int WARPS_M = 8 / WARPS_N;
    constexpr int WM = BM / WARPS_M;
    constexpr int WN = BN / WARPS_N;
    constexpr int MT = WM / 16;
    constexpr int NT = WN / 8;
    constexpr int AP = BM + 8;
    constexpr int BP = BN + 8;

    __shared__ float As[2][BK][AP];
    __shared__ float Bs[2][BK][BP];

    int tid = threadIdx.x;
    int warp = tid >> 5;
    int lane = tid & 31;
    int g  = lane >> 2;
    int tg = lane & 3;
    int warpM = warp % WARPS_M;
    int warpN = warp / WARPS_M;

    float acc[MT][NT][4];
#pragma unroll
    for (int i = 0; i < MT; i++)
#pragma unroll
        for (int j = 0; j < NT; j++)
#pragma unroll
            for (int c = 0; c < 4; c++) acc[i][j][c] = 0.f;

    int arow = tid >> 1, ak = (tid & 1) * 8;
    int acol = ac16(arow);
    int br128 = tid >> 5, bc128 = (tid & 31) * 4;
    int br64  = tid >> 4, bc64  = (tid & 15) * 4;

    float4 ra0, ra1, rb0, rb1;

    auto loadA = [&](int k0) {
        const float* ap = A + (size_t)(m0 + arow) * K + k0 + ak;
        ra0 = *(const float4*)ap;
        ra1 = *(const float4*)(ap + 4);
    };
    auto loadB = [&](int k0) {
        if (BN == 128) {
            if (BALIGN) {
                rb0 = *(const float4*)(Bm + (size_t)(k0 + br128) * N + n0 + bc128);
                rb1 = *(const float4*)(Bm + (size_t)(k0 + br128 + 8) * N + n0 + bc128);
            } else {
                const float* bp0 = Bm + (size_t)(k0 + br128) * N;
                const float* bp1 = Bm + (size_t)(k0 + br128 + 8) * N;
                int c0 = n0 + bc128;
                rb0.x = (c0 + 0 < N) ? bp0[c0 + 0] : 0.f;
                rb0.y = (c0 + 1 < N) ? bp0[c0 + 1] : 0.f;
                rb0.z = (c0 + 2 < N) ? bp0[c0 + 2] : 0.f;
                rb0.w = (c0 + 3 < N) ? bp0[c0 + 3] : 0.f;
                rb1.x = (c0 + 0 < N) ? bp1[c0 + 0] : 0.f;
                rb1.y = (c0 + 1 < N) ? bp1[c0 + 1] : 0.f;
                rb1.z = (c0 + 2 < N) ? bp1[c0 + 2] : 0.f;
                rb1.w = (c0 + 3 < N) ? bp1[c0 + 3] : 0.f;
            }
        } else {
            rb0 = *(const float4*)(Bm + (size_t)(k0 + br64) * N + n0 + bc64);
        }
    };
    auto storeA = [&](int s) {
        As[s][ak + 0][acol] = to_tf32(ra0.x); As[s][ak + 1][acol] = to_tf32(ra0.y);
        As[s][ak + 2][acol] = to_tf32(ra0.z); As[s][ak + 3][acol] = to_tf32(ra0.w);
        As[s][ak + 4][acol] = to_tf32(ra1.x); As[s][ak + 5][acol] = to_tf32(ra1.y);
        As[s][ak + 6][acol] = to_tf32(ra1.z); As[s][ak + 7][acol] = to_tf32(ra1.w);
    };
    auto storeB = [&](int s) {
        if (BN == 128) {
            Bs[s][br128][bc32(bc128 + 0)] = to_tf32(rb0.x);
            Bs[s][br128][bc32(bc128 + 1)] = to_tf32(rb0.y);
            Bs[s][br128][bc32(bc128 + 2)] = to_tf32(rb0.z);
            Bs[s][br128][bc32(bc128 + 3)] = to_tf32(rb0.w);
            Bs[s][br128 + 8][bc32(bc128 + 0)] = to_tf32(rb1.x);
            Bs[s][br128 + 8][bc32(bc128 + 1)] = to_tf32(rb1.y);
            Bs[s][br128 + 8][bc32(bc128 + 2)] = to_tf32(rb1.z);
            Bs[s][br128 + 8][bc32(bc128 + 3)] = to_tf32(rb1.w);
        } else {
            Bs[s][br64][bc32(bc64 + 0)] = to_tf32(rb0.x);
            Bs[s][br64][bc32(bc64 + 1)] = to_tf32(rb0.y);
            Bs[s][br64][bc32(bc64 + 2)] = to_tf32(rb0.z);
            Bs[s][br64][bc32(bc64 + 3)] = to_tf32(rb0.w);
        }
    };

    int nTiles = K / BK;
    loadA(0); loadB(0);
    storeA(0); storeB(0);
    __syncthreads();

    for (int t = 0; t < nTiles; t++) {
        int cur = t & 1, nxt = cur ^ 1;
        bool more = (t + 1 < nTiles);
        if (more) { loadA((t + 1) * BK); loadB((t + 1) * BK); }

#pragma unroll
        for (int kk = 0; kk < BK; kk += 8) {
            uint32_t afr[MT][4];
            float bfr0[NT], bfr1[NT];
#pragma unroll
            for (int mt = 0; mt < MT; mt++) {
                int mc = warpM * WM + mt * 16 + g * 2;
                float2 x0 = *(const float2*)&As[cur][kk + tg][mc];
                float2 x1 = *(const float2*)&As[cur][kk + tg + 4][mc];
                afr[mt][0] = __float_as_uint(x0.x);
                afr[mt][1] = __float_as_uint(x0.y);
                afr[mt][2] = __float_as_uint(x1.x);
                afr[mt][3] = __float_as_uint(x1.y);
            }
            {
                int nc = warpN * WN + g * 4;
                float4 b0 = *(const float4*)&Bs[cur][kk + tg][nc];
                float4 b1 = *(const float4*)&Bs[cur][kk + tg + 4][nc];
                bfr0[0] = b0.x; bfr0[1] = b0.y; bfr0[2] = b0.z; bfr0[3] = b0.w;
                bfr1[0] = b1.x; bfr1[1] = b1.y; bfr1[2] = b1.z; bfr1[3] = b1.w;
            }
#pragma unroll
            for (int mt = 0; mt < MT; mt++)
#pragma unroll
                for (int nt = 0; nt < NT; nt++) {
                    asm volatile(
                        "mma.sync.aligned.m16n8k8.row.col.f32.tf32.tf32.f32 "
                        "{%0,%1,%2,%3}, {%4,%5,%6,%7}, {%8,%9}, {%0,%1,%2,%3};"
                        : "+f"(acc[mt][nt][0]), "+f"(acc[mt][nt][1]),
                          "+f"(acc[mt][nt][2]), "+f"(acc[mt][nt][3])
                        : "r"(afr[mt][0]), "r"(afr[mt][1]),
                          "r"(afr[mt][2]), "r"(afr[mt][3]),
                          "r"(__float_as_uint(bfr0[nt])), "r"(__float_as_uint(bfr1[nt])));
                }
        }
        if (more) { storeA(nxt); storeB(nxt); }
        __syncthreads();
    }

#pragma unroll
    for (int mt = 0; mt < MT; mt++) {
#pragma unroll
        for (int nt = 0; nt < NT; nt++) {
            int row0 = m0 + warpM * WM + mt * 16 + g;
            int col0 = n0 + warpN * WN + nt * 8 + 2 * tg;
#pragma unroll
            for (int hh = 0; hh < 2; hh++) {
                int row = row0 + hh * 8;
#pragma unroll
                for (int j = 0; j < 2; j++) {
                    int col = col0 + j;
                    if (col < N) {
                        float v = acc[mt][nt][hh * 2 + j];
                        if (HAS_BIAS) v += bias[col];
                        if (ACT == 1) v = 0.5f * v * (1.0f + erff(v * 0.70710678118654752f));
                        if (HAS_RES) v += Res[(size_t)row * N + col];
                        C[(size_t)row * N + col] = v;
                    }
                }
            }
        }
    }

    // ---- loss partials: per-row online (max, sumexp) over this N-slice ------
    if (LOSSP) {
        float2* red = (float2*)&As[0][0][0];   // 128 rows x WARPS_N, reuse smem
        // main loop ended with __syncthreads(); epilogue above touched no smem.
#pragma unroll
        for (int mt = 0; mt < MT; mt++) {
#pragma unroll
            for (int hh = 0; hh < 2; hh++) {
                float mx = -1e30f, sm = 0.f;
#pragma unroll
                for (int nt = 0; nt < NT; nt++) {
#pragma unroll
                    for (int j = 0; j < 2; j++) {
                        int col = n0 + warpN * WN + nt * 8 + 2 * tg + j;
                        if (col < N) {
                            float v = acc[mt][nt][hh * 2 + j];
                            if (v > mx) { sm = sm * __expf(mx - v) + 1.f; mx = v; }
                            else        { sm += __expf(v - mx); }
                        }
                    }
                }
                // merge across the 4 tg lanes (same row)
#pragma unroll
                for (int d = 1; d <= 2; d <<= 1) {
                    float mx2 = __shfl_xor_sync(0xffffffffu, mx, d);
                    float sm2 = __shfl_xor_sync(0xffffffffu, sm, d);
                    float M2 = fmaxf(mx, mx2);
                    sm = sm * __expf(mx - M2) + sm2 * __expf(mx2 - M2);
                    mx = M2;
                }
                if (tg == 0) {
                    int lr = warpM * WM + mt * 16 + g + hh * 8;   // 0..127
                    red[lr * WARPS_N + warpN] = make_float2(mx, sm);
                }
            }
        }
        __syncthreads();
        if (tid < BM) {
            float mx = -1e30f, sm = 0.f;
#pragma unroll
            for (int w = 0; w < WARPS_N; w++) {
                float2 p = red[tid * WARPS_N + w];
                float M2 = fmaxf(mx, p.x);
                sm = sm * __expf(mx - M2) + p.y * __expf(p.x - M2);
                mx = M2;
            }
            part[(size_t)(m0 + tid) * PSTRIDE + (n0 / BN)] = make_float2(mx, sm);
        }
    }
}

template <int ACT, bool HAS_BIAS, bool HAS_RES, int BN, bool BALIGN, bool SWAP, bool LOSSP>
__global__ __launch_bounds__(256) void gemm_tc(const float* __restrict__ A,
                                               const float* __restrict__ Bm,
                                               const float* __restrict__ bias,
                                               const float* __restrict__ Res,
                                               float* __restrict__ C,
                                               float2* __restrict__ part,
                                               int M, int N, int K) {
    int m0 = (SWAP ? blockIdx.x : blockIdx.y) * 128;
    int n0 = (SWAP ? blockIdx.y : blockIdx.x) * BN;
    gemm_body<ACT, HAS_BIAS, HAS_RES, BN, BALIGN, LOSSP>(A, Bm, bias, Res, C, part, M, N, K, m0, n0);
}

struct TriPtrs {
    const float* w[3];
    const float* b[3];
    float*       c[3];
};
__global__ __launch_bounds__(256) void gemm_qkv(const float* __restrict__ A,
                                                TriPtrs t, int M, int N, int K) {
    int z = blockIdx.z;
    gemm_body<0, true, false, 64, true, false>(
        A, t.w[z], t.b[z], nullptr, t.c[z], nullptr, M, N, K, blockIdx.y * 128, blockIdx.x * 64);
}

// ---------------- fully fused flash attention, 2 warp-groups (split-K) -------
__global__ __launch_bounds__(256) void attn_flash(const float* __restrict__ Q,
                                                  const float* __restrict__ Kg,
                                                  const float* __restrict__ Vg,
                                                  float* __restrict__ O) {
    __shared__ __align__(16) float sm[9344];

    int q0 = (gridDim.x - 1 - blockIdx.x) * 64;   // longest first
    int bh = blockIdx.y;
    int b = bh >> 3, h = bh & 7;
    int tid = threadIdx.x;
    int warp = tid >> 5;
    int grp = warp >> 2;
    int wl = warp & 3;
    int lane = tid & 31;
    int gl = lane >> 2, tg = lane & 3;
    int m0 = wl * 16;
    int lt = tid & 127;

    const float* qbase = Q + (size_t)b * NS * ND + h * NDH;
    const float* kbase = Kg + (size_t)b * NS * ND + h * NDH;
    const float* vbase = Vg + (size_t)b * NS * ND + h * NDH;

    {
        int row = tid >> 2;
        int doff = (tid & 3) * 16;
        int acol = ac16(row);
        const float* qp = qbase + (size_t)(q0 + row) * ND + doff;
#pragma unroll
        for (int j = 0; j < 4; j++) {
            float4 f = *(const float4*)(qp + j * 4);
            sm[(doff + j * 4 + 0) * 72 + acol] = to_tf32(f.x);
            sm[(doff + j * 4 + 1) * 72 + acol] = to_tf32(f.y);
            sm[(doff + j * 4 + 2) * 72 + acol] = to_tf32(f.z);
            sm[(doff + j * 4 + 3) * 72 + acol] = to_tf32(f.w);
        }
    }
    __syncthreads();

    uint32_t qfr[8][4];
#pragma unroll
    for (int ks = 0; ks < 8; ks++) {
        int kk = ks * 8;
        float2 x0 = *(const float2*)&sm[(kk + tg) * 72 + m0 + 2 * gl];
        float2 x1 = *(const float2*)&sm[(kk + tg + 4) * 72 + m0 + 2 * gl];
        qfr[ks][0] = __float_as_uint(x0.x);
        qfr[ks][1] = __float_as_uint(x0.y);
        qfr[ks][2] = __float_as_uint(x1.x);
        qfr[ks][3] = __float_as_uint(x1.y);
    }
    __syncthreads();

    float* Ksm = sm + grp * 2304;
    float* Psm = Ksm;
    float* Vsm = sm + 4608 + grp * 2304;
    float* m1_s = sm + 9216;
    float* l1_s = sm + 9280;

    float Oacc[8][4];
#pragma unroll
    for (int nt = 0; nt < 8; nt++)
#pragma unroll
        for (int c = 0; c < 4; c++) Oacc[nt][c] = 0.f;

    float mo0 = -1e30f, mo1 = -1e30f, l0 = 0.f, l1 = 0.f;
    int qr0 = q0 + m0 + gl, qr1 = qr0 + 8;
    int pc0 = m0 + 2 * gl, pc1 = pc0 + 1;

    int nblk = (q0 + 64) >> 5;
    int barid = 1 + grp;

    for (int blk = grp; blk < nblk; blk += 2) {
        int kc = blk << 5;
        {
            int ktok = lt & 31;
            int kdoff = (lt >> 5) * 16;
            int bcol = bc32(ktok);
            const float* kp = kbase + (size_t)(kc + ktok) * ND + kdoff;
#pragma unroll
            for (int j = 0; j < 4; j++) {
                float4 f = *(const float4*)(kp + j * 4);
                Ksm[(kdoff + j * 4 + 0) * 36 + bcol] = to_tf32(f.x);
                Ksm[(kdoff + j * 4 + 1) * 36 + bcol] = to_tf32(f.y);
                Ksm[(kdoff + j * 4 + 2) * 36 + bcol] = to_tf32(f.z);
                Ksm[(kdoff + j * 4 + 3) * 36 + bcol] = to_tf32(f.w);
            }
        }
        {
            int vtok = lt >> 2;
            int vdoff = (lt & 3) * 16;
            const float* vp = vbase + (size_t)(kc + vtok) * ND + vdoff;
#pragma unroll
            for (int j = 0; j < 4; j++) {
                float4 f = *(const float4*)(vp + j * 4);
                Vsm[vtok * 72 + bc64p(vdoff + j * 4 + 0)] = to_tf32(f.x);
                Vsm[vtok * 72 + bc64p(vdoff + j * 4 + 1)] = to_tf32(f.y);
                Vsm[vtok * 72 + bc64p(vdoff + j * 4 + 2)] = to_tf32(f.z);
                Vsm[vtok * 72 + bc64p(vdoff + j * 4 + 3)] = to_tf32(f.w);
            }
        }
        asm volatile("bar.sync %0, 128;" :: "r"(barid) : "memory");

        float s[4][4];
#pragma unroll
        for (int nt = 0; nt < 4; nt++)
#pragma unroll
            for (int c = 0; c < 4; c++) s[nt][c] = 0.f;
#pragma unroll
        for (int ks = 0; ks < 8; ks++) {
            int kk = ks * 8;
            float4 b0 = *(const float4*)&Ksm[(kk + tg) * 36 + gl * 4];
            float4 b1 = *(const float4*)&Ksm[(kk + tg + 4) * 36 + gl * 4];
            float bf0[4] = {b0.x, b0.y, b0.z, b0.w};
            float bf1[4] = {b1.x, b1.y, b1.z, b1.w};
#pragma unroll
            for (int nt = 0; nt < 4; nt++) {
                asm volatile(
                    "mma.sync.aligned.m16n8k8.row.col.f32.tf32.tf32.f32 "
                    "{%0,%1,%2,%3}, {%4,%5,%6,%7}, {%8,%9}, {%0,%1,%2,%3};"
                    : "+f"(s[nt][0]), "+f"(s[nt][1]), "+f"(s[nt][2]), "+f"(s[nt][3])
                    : "r"(qfr[ks][0]), "r"(qfr[ks][1]), "r"(qfr[ks][2]), "r"(qfr[ks][3]),
                      "r"(__float_as_uint(bf0[nt])), "r"(__float_as_uint(bf1[nt])));
            }
        }
#pragma unroll
        for (int nt = 0; nt < 4; nt++)
#pragma unroll
            for (int c = 0; c < 4; c++) s[nt][c] *= INV_SCALE;
        if (kc + 31 > q0) {
#pragma unroll
            for (int nt = 0; nt < 4; nt++) {
                int kb = kc + nt * 8 + 2 * tg;
                if (kb > qr0)     s[nt][0] = -INFINITY;
                if (kb + 1 > qr0) s[nt][1] = -INFINITY;
                if (kb > qr1)     s[nt][2] = -INFINITY;
                if (kb + 1 > qr1) s[nt][3] = -INFINITY;
            }
        }
        float mb0 = fmaxf(fmaxf(s[0][0], s[0][1]), fmaxf(s[1][0], s[1][1]));
        mb0 = fmaxf(mb0, fmaxf(fmaxf(s[2][0], s[2][1]), fmaxf(s[3][0], s[3][1])));
        float mb1 = fmaxf(fmaxf(s[0][2], s[0][3]), fmaxf(s[1][2], s[1][3]));
        mb1 = fmaxf(mb1, fmaxf(fmaxf(s[2][2], s[2][3]), fmaxf(s[3][2], s[3][3])));
        mb0 = fmaxf(mb0, __shfl_xor_sync(0xffffffffu, mb0, 1));
        mb0 = fmaxf(mb0, __shfl_xor_sync(0xffffffffu, mb0, 2));
        mb1 = fmaxf(mb1, __shfl_xor_sync(0xffffffffu, mb1, 1));
        mb1 = fmaxf(mb1, __shfl_xor_sync(0xffffffffu, mb1, 2));
        float mn0 = fmaxf(mo0, mb0), mn1 = fmaxf(mo1, mb1);
        float fc0 = __expf(mo0 - mn0), fc1 = __expf(mo1 - mn1);
        float e[4][4];
        float ps0 = 0.f, ps1 = 0.f;
#pragma unroll
        for (int nt = 0; nt < 4; nt++) {
            e[nt][0] = __expf(s[nt][0] - mn0);
            e[nt][1] = __expf(s[nt][1] - mn0);
            e[nt][2] = __expf(s[nt][2] - mn1);
            e[nt][3] = __expf(s[nt][3] - mn1);
            ps0 += e[nt][0] + e[nt][1];
            ps1 += e[nt][2] + e[nt][3];
        }
        ps0 += __shfl_xor_sync(0xffffffffu, ps0, 1);
        ps0 += __shfl_xor_sync(0xffffffffu, ps0, 2);
        ps1 += __shfl_xor_sync(0xffffffffu, ps1, 1);
        ps1 += __shfl_xor_sync(0xffffffffu, ps1, 2);
        l0 = l0 * fc0 + ps0; l1 = l1 * fc1 + ps1;
        mo0 = mn0; mo1 = mn1;
#pragma unroll
        for (int nt = 0; nt < 8; nt++) {
            Oacc[nt][0] *= fc0; Oacc[nt][1] *= fc0;
            Oacc[nt][2] *= fc1; Oacc[nt][3] *= fc1;
        }

        asm volatile("bar.sync %0, 128;" :: "r"(barid) : "memory");
#pragma unroll
        for (int nt = 0; nt < 4; nt++) {
            int kr = nt * 8 + 2 * tg;
            Psm[(kr)     * 72 + pc0] = to_tf32(e[nt][0]);
            Psm[(kr + 1) * 72 + pc0] = to_tf32(e[nt][1]);
            Psm[(kr)     * 72 + pc1] = to_tf32(e[nt][2]);
            Psm[(kr + 1) * 72 + pc1] = to_tf32(e[nt][3]);
        }
        __syncwarp();

#pragma unroll
        for (int ks = 0; ks < 4; ks++) {
            int kk = ks * 8;
            float2 x0 = *(const float2*)&Psm[(kk + tg) * 72 + pc0];
            float2 x1 = *(const float2*)&Psm[(kk + tg + 4) * 72 + pc0];
            uint32_t a0 = __float_as_uint(x0.x), a1 = __float_as_uint(x0.y);
            uint32_t a2 = __float_as_uint(x1.x), a3 = __float_as_uint(x1.y);
            float4 b0lo = *(const float4*)&Vsm[(kk + tg) * 72 + gl * 8];
            float4 b0hi = *(const float4*)&Vsm[(kk + tg) * 72 + gl * 8 + 4];
            float4 b1lo = *(const float4*)&Vsm[(kk + tg + 4) * 72 + gl * 8];
            float4 b1hi = *(const float4*)&Vsm[(kk + tg + 4) * 72 + gl * 8 + 4];
            float bf0[8] = {b0lo.x, b0lo.y, b0lo.z, b0lo.w, b0hi.x, b0hi.y, b0hi.z, b0hi.w};
            float bf1[8] = {b1lo.x, b1lo.y, b1lo.z, b1lo.w, b1hi.x, b1hi.y, b1hi.z, b1hi.w};
#pragma unroll
            for (int nt = 0; nt < 8; nt++) {
                asm volatile(
                    "mma.sync.aligned.m16n8k8.row.col.f32.tf32.tf32.f32 "
                    "{%0,%1,%2,%3}, {%4,%5,%6,%7}, {%8,%9}, {%0,%1,%2,%3};"
                    : "+f"(Oacc[nt][0]), "+f"(Oacc[nt][1]), "+f"(Oacc[nt][2]), "+f"(Oacc[nt][3])
                    : "r"(a0), "r"(a1), "r"(a2), "r"(a3),
                      "r"(__float_as_uint(bf0[nt])), "r"(__float_as_uint(bf1[nt])));
            }
        }
        asm volatile("bar.sync %0, 128;" :: "r"(barid) : "memory");
    }

    __syncthreads();
    int r0 = m0 + gl, r1 = r0 + 8;
    if (grp == 1) {
        if (tg == 0) {
            m1_s[r0] = mo0; m1_s[r1] = mo1;
            l1_s[r0] = l0;  l1_s[r1] = l1;
        }
#pragma unroll
        for (int nt = 0; nt < 8; nt++) {
            int d = nt * 8 + 2 * tg;
            *(float2*)&sm[r0 * 72 + d] = make_float2(Oacc[nt][0], Oacc[nt][1]);
            *(float2*)&sm[r1 * 72 + d] = make_float2(Oacc[nt][2], Oacc[nt][3]);
        }
    }
    __syncthreads();
    if (grp == 0) {
        float m1v0 = m1_s[r0], m1v1 = m1_s[r1];
        float l1v0 = l1_s[r0], l1v1 = l1_s[r1];
        float mf0 = fmaxf(mo0, m1v0), mf1 = fmaxf(mo1, m1v1);
        float a0c = __expf(mo0 - mf0), b0c = __expf(m1v0 - mf0);
        float a1c = __expf(mo1 - mf1), b1c = __expf(m1v1 - mf1);
        float inv0 = 1.0f / (l0 * a0c + l1v0 * b0c);
        float inv1 = 1.0f / (l1 * a1c + l1v1 * b1c);
        float* ob = O + (size_t)b * NS * ND + h * NDH;
#pragma unroll
        for (int nt = 0; nt < 8; nt++) {
            int d = nt * 8 + 2 * tg;
            float2 o10 = *(const float2*)&sm[r0 * 72 + d];
            float2 o11 = *(const float2*)&sm[r1 * 72 + d];
            float2 w0 = make_float2((Oacc[nt][0] * a0c + o10.x * b0c) * inv0,
                                    (Oacc[nt][1] * a0c + o10.y * b0c) * inv0);
            float2 w1 = make_float2((Oacc[nt][2] * a1c + o11.x * b1c) * inv1,
                                    (Oacc[nt][3] * a1c + o11.y * b1c) * inv1);
            *(float2*)&ob[(size_t)qr0 * ND + d] = w0;
            *(float2*)&ob[(size_t)qr1 * ND + d] = w1;
        }
    }
}

// ---------------- loss from per-tile partials --------------------------------
__global__ __launch_bounds__(512) void loss_row2(const float2* __restrict__ part,
                                                 const float* __restrict__ logits,
                                                 const int* __restrict__ idx,
                                                 const int* __restrict__ mask,
                                                 float* __restrict__ nll) {
    int row = blockIdx.x;
    int b = row / NS, s = row % NS;
    int tid = threadIdx.x;
    __shared__ float redm[512];
    __shared__ float reds[512];
    float m = -1e30f, sum = 0.f;
    if (tid < NPART) {
        float2 p = part[(size_t)row * PSTRIDE + tid];
        m = p.x; sum = p.y;
    }
    redm[tid] = m; reds[tid] = sum;
    __syncthreads();
    for (int o = 256; o > 0; o >>= 1) {
        if (tid < o) {
            float m2 = redm[tid + o], s2 = reds[tid + o];
            float m1 = redm[tid],     s1 = reds[tid];
            float M = fmaxf(m1, m2);
            redm[tid] = M;
            reds[tid] = s1 * __expf(m1 - M) + s2 * __expf(m2 - M);
        }
        __syncthreads();
    }
    if (tid == 0) {
        int tgt = idx[b * (NS + 1) + s + 1];
        float lse = redm[0] + logf(reds[0]);
        nll[row] = (lse - logits[(size_t)row * NV + tgt]) * (float)mask[row];
    }
}

__global__ __launch_bounds__(1024) void loss_final_k(const float* __restrict__ nll,
                                                     float* __restrict__ out) {
    __shared__ float red[1024];
    int tid = threadIdx.x;
    red[tid] = nll[tid] + nll[tid + 1024];
    __syncthreads();
    for (int o = 512; o > 0; o >>= 1) { if (tid < o) red[tid] += red[tid + o]; __syncthreads(); }
    if (tid == 0) out[0] = red[0] * (1.0f / (float)NBS);
}

// ---------------- host orchestration -----------------------------------------
extern "C" void kernel_launch(void* const* d_in, const int* in_sizes, int n_in,
                              void* d_out, int out_size) {
    const int*   idx  = (const int*)d_in[0];
    const int*   mask = (const int*)d_in[1];
    const float* tok  = (const float*)d_in[2];
    const float* pos  = (const float*)d_in[3];
    const float* Wq   = (const float*)d_in[4];
    const float* bq   = (const float*)d_in[5];
    const float* Wk   = (const float*)d_in[6];
    const float* bk   = (const float*)d_in[7];
    const float* Wv   = (const float*)d_in[8];
    const float* bv   = (const float*)d_in[9];
    const float* Wo   = (const float*)d_in[10];
    const float* bo   = (const float*)d_in[11];
    const float* ln1g = (const float*)d_in[12];
    const float* ln1b = (const float*)d_in[13];
    const float* W1   = (const float*)d_in[14];
    const float* b1   = (const float*)d_in[15];
    const float* W2   = (const float*)d_in[16];
    const float* b2   = (const float*)d_in[17];
    const float* ln2g = (const float*)d_in[18];
    const float* ln2b = (const float*)d_in[19];
    const float* lnfg = (const float*)d_in[20];
    const float* lnfb = (const float*)d_in[21];
    const float* headw= (const float*)d_in[22];
    float* out = (float*)d_out;

    float *x, *h, *q, *k, *v, *o, *ff, *nll;
    float2* part;
    cudaGetSymbolAddress((void**)&x,    g_x);
    cudaGetSymbolAddress((void**)&h,    g_h);
    cudaGetSymbolAddress((void**)&q,    g_q);
    cudaGetSymbolAddress((void**)&k,    g_k);
    cudaGetSymbolAddress((void**)&v,    g_v);
    cudaGetSymbolAddress((void**)&o,    g_o);
    cudaGetSymbolAddress((void**)&ff,   g_ff);
    cudaGetSymbolAddress((void**)&part, g_part);
    cudaGetSymbolAddress((void**)&nll,  g_nll);

    embed_k<<<NBS, 256>>>(idx, mask, tok, pos, x);

    dim3 gQKV(ND / 64, NBS / 128, 3);   // 384 CTAs
    dim3 gDD(ND / 64, NBS / 128);       // 128 CTAs
    dim3 gDF(NFF / 128, NBS / 128);     // 256 CTAs
    dim3 gFA(NS / 64, NB * NH);         // 256 CTAs x 256 thr

    for (int l = 0; l < NL; l++) {
        const float* wq = Wq + (size_t)l * ND * ND;
        const float* wk = Wk + (size_t)l * ND * ND;
        const float* wv = Wv + (size_t)l * ND * ND;
        const float* wo = Wo + (size_t)l * ND * ND;
        const float* w1 = W1 + (size_t)l * ND * NFF;
        const float* w2 = W2 + (size_t)l * NFF * ND;

        ln_k<<<NBS, 256>>>(x, ln1g + l * ND, ln1b + l * ND, h);
        TriPtrs t;
        t.w[0] = wq; t.w[1] = wk; t.w[2] = wv;
        t.b[0] = bq + l * ND; t.b[1] = bk + l * ND; t.b[2] = bv + l * ND;
        t.c[0] = q; t.c[1] = k; t.c[2] = v;
        gemm_qkv<<<gQKV, 256>>>(h, t, NBS, ND, ND);
        attn_flash<<<gFA, 256>>>(q, k, v, o);
        gemm_tc<0, true, true, 64, true, false, false><<<gDD, 256>>>(o, wo, bo + l * ND, x, x, nullptr, NBS, ND, ND);
        ln_k<<<NBS, 256>>>(x, ln2g + l * ND, ln2b + l * ND, h);
        gemm_tc<1, true, false, 128, true, false, false><<<gDF, 256>>>(h, w1, b1 + l * NFF, nullptr, ff, nullptr, NBS, NFF, ND);
        gemm_tc<0, true, true, 64, true, false, false><<<gDD, 256>>>(ff, w2, b2 + l * ND, x, x, nullptr, NBS, ND, NFF);
    }

    ln_k<<<NBS, 256>>>(x, lnfg, lnfb, h);
    dim3 gHead(NBS / 128, (NV + 127) / 128);   // M-tiles fastest -> B reused in L2
    gemm_tc<0, false, false, 128, false, true, true><<<gHead, 256>>>(h, headw, nullptr, nullptr, out, part, NBS, NV, ND);

    loss_row2<<<NBS, 512>>>(part, out, idx, mask, nll);
    loss_final_k<<<1, 1024>>>(nll, out + (size_t)NBS * NV);
}